// round 1
// baseline (speedup 1.0000x reference)
#include <cuda_runtime.h>

// Problem constants
#define BB 16
#define CC 64
#define HH 256
#define WW 256
#define HW (HH*WW)
#define KPOS 9          // 3x3
#define JDIM (CC*KPOS)  // 576

// Scratch (no allocation allowed in kernel_launch)
__device__ float g_avg[BB*CC];          // 1024
__device__ float g_wk[BB*JDIM];         // 9216 sigmoid'd dynamic weights

// ---------------------------------------------------------------------------
// Kernel 1: per-(b,c) spatial mean. One block per (b,c) plane (65536 floats).
// ---------------------------------------------------------------------------
__global__ void avg_kernel(const float* __restrict__ x) {
    const int bc = blockIdx.x;
    const float4* p = reinterpret_cast<const float4*>(x + (size_t)bc * HW);
    const int t = threadIdx.x;     // 0..255
    float s = 0.f;
    // 16384 float4 per plane; 64 per thread, coalesced (stride 256 vecs)
    #pragma unroll 8
    for (int i = 0; i < 64; ++i) {
        float4 v = p[i * 256 + t];
        s += (v.x + v.y) + (v.z + v.w);
    }
    __shared__ float red[256];
    red[t] = s;
    __syncthreads();
    #pragma unroll
    for (int off = 128; off > 0; off >>= 1) {
        if (t < off) red[t] += red[t + off];
        __syncthreads();
    }
    if (t == 0) g_avg[bc] = red[0] * (1.0f / (float)HW);
}

// ---------------------------------------------------------------------------
// Kernel 2: dyn = avg @ w1^T + b1 ; wk = sigmoid(dyn).
// w1 is (576, 64) row-major. One block per batch, one thread per j.
// ---------------------------------------------------------------------------
__global__ void weight_kernel(const float* __restrict__ w1,
                              const float* __restrict__ b1) {
    const int b = blockIdx.x;
    const int j = threadIdx.x;   // 0..575
    __shared__ float av[CC];
    if (j < CC) av[j] = g_avg[b * CC + j];
    __syncthreads();
    float s = b1[j];
    const float* wr = w1 + (size_t)j * CC;
    #pragma unroll 16
    for (int c = 0; c < CC; ++c) s += av[c] * wr[c];
    g_wk[b * JDIM + j] = 1.0f / (1.0f + expf(-s));
}

// ---------------------------------------------------------------------------
// Kernel 3: depthwise 3x3 conv (zero pad, correlation) + conv_bias, fused with
// out = (x - y) * fscale * x + y.
// Block: 256 threads handle a 16-row x 256-col tile of one (b,c) plane.
// Smem tile: 18 rows x 258 cols (1-col halo each side, zeroed).
// ---------------------------------------------------------------------------
#define TR 16
#define SWD 258

__global__ void conv_kernel(const float* __restrict__ x,
                            const float* __restrict__ fscale,
                            const float* __restrict__ conv_bias,
                            float* __restrict__ out) {
    const int bc   = blockIdx.y;          // 0..1023
    const int c    = bc & (CC - 1);
    const int row0 = blockIdx.x * TR;
    const int t    = threadIdx.x;         // 0..255

    __shared__ float sm[(TR + 2) * SWD];
    __shared__ float wsh[KPOS];

    if (t < KPOS) wsh[t] = g_wk[bc * KPOS + t];
    if (t < TR + 2) {                      // zero column halos
        sm[t * SWD + 0]   = 0.f;
        sm[t * SWD + 257] = 0.f;
    }

    const float* xp = x + (size_t)bc * HW;
    // Load 18 rows x 64 float4 (zero rows outside the image)
    for (int i = t; i < (TR + 2) * 64; i += 256) {
        const int r  = i >> 6;
        const int c4 = i & 63;
        const int g  = row0 - 1 + r;
        float4 v = make_float4(0.f, 0.f, 0.f, 0.f);
        if ((unsigned)g < HH)
            v = reinterpret_cast<const float4*>(xp + (size_t)g * WW)[c4];
        float* d = &sm[r * SWD + 1 + c4 * 4];
        d[0] = v.x; d[1] = v.y; d[2] = v.z; d[3] = v.w;
    }
    __syncthreads();

    const float w0 = wsh[0], w1v = wsh[1], w2 = wsh[2];
    const float w3 = wsh[3], w4  = wsh[4], w5 = wsh[5];
    const float w6 = wsh[6], w7  = wsh[7], w8 = wsh[8];
    const float cb = conv_bias[c];
    const float fs = fscale[c];

    const int col = t;   // 0..255; smem index for dx=-1 is r*SWD + col
    float t0 = sm[col],        t1 = sm[col + 1],        t2 = sm[col + 2];
    float m0 = sm[SWD + col],  m1 = sm[SWD + col + 1],  m2 = sm[SWD + col + 2];

    float* op = out + (size_t)bc * HW + (size_t)row0 * WW + col;

    #pragma unroll
    for (int r = 0; r < TR; ++r) {
        const int sr = (r + 2) * SWD + col;
        const float b0 = sm[sr], b1e = sm[sr + 1], b2 = sm[sr + 2];
        float y = cb;
        y += w0 * t0 + w1v * t1 + w2 * t2;
        y += w3 * m0 + w4  * m1 + w5 * m2;
        y += w6 * b0 + w7  * b1e + w8 * b2;
        const float xv = m1;                       // center pixel
        op[r * WW] = (xv - y) * fs * xv + y;
        t0 = m0; t1 = m1; t2 = m2;
        m0 = b0; m1 = b1e; m2 = b2;
    }
}

// ---------------------------------------------------------------------------
// Launch: x, w1, b1, fscale, conv_bias (metadata order); out fp32.
// ---------------------------------------------------------------------------
extern "C" void kernel_launch(void* const* d_in, const int* in_sizes, int n_in,
                              void* d_out, int out_size) {
    const float* x         = (const float*)d_in[0];
    const float* w1        = (const float*)d_in[1];
    const float* b1        = (const float*)d_in[2];
    const float* fscale    = (const float*)d_in[3];
    const float* conv_bias = (const float*)d_in[4];
    float* out = (float*)d_out;

    avg_kernel<<<BB * CC, 256>>>(x);
    weight_kernel<<<BB, JDIM>>>(w1, b1);
    conv_kernel<<<dim3(HH / TR, BB * CC), 256>>>(x, fscale, conv_bias, out);
}

// round 2
// speedup vs baseline: 1.0241x; 1.0241x over previous
#include <cuda_runtime.h>

// Problem constants
#define BB 16
#define CC 64
#define HH 256
#define WW 256
#define HW (HH*WW)
#define KPOS 9          // 3x3
#define JDIM (CC*KPOS)  // 576

// Scratch (no allocation allowed in kernel_launch)
__device__ float g_avg[BB*CC];          // 1024
__device__ float g_wk[BB*JDIM];         // 9216 sigmoid'd dynamic weights

// ---------------------------------------------------------------------------
// Kernel 1: per-(b,c) spatial mean. One block per (b,c) plane (65536 floats).
// Already at DRAM roofline (81% / 6.45 TB/s) — unchanged.
// ---------------------------------------------------------------------------
__global__ void avg_kernel(const float* __restrict__ x) {
    const int bc = blockIdx.x;
    const float4* p = reinterpret_cast<const float4*>(x + (size_t)bc * HW);
    const int t = threadIdx.x;     // 0..255
    float s = 0.f;
    #pragma unroll 8
    for (int i = 0; i < 64; ++i) {
        float4 v = p[i * 256 + t];
        s += (v.x + v.y) + (v.z + v.w);
    }
    __shared__ float red[256];
    red[t] = s;
    __syncthreads();
    #pragma unroll
    for (int off = 128; off > 0; off >>= 1) {
        if (t < off) red[t] += red[t + off];
        __syncthreads();
    }
    if (t == 0) g_avg[bc] = red[0] * (1.0f / (float)HW);
}

// ---------------------------------------------------------------------------
// Kernel 2: dyn = avg @ w1^T + b1 ; wk = sigmoid(dyn).
// ---------------------------------------------------------------------------
__global__ void weight_kernel(const float* __restrict__ w1,
                              const float* __restrict__ b1) {
    const int b = blockIdx.x;
    const int j = threadIdx.x;   // 0..575
    __shared__ float av[CC];
    if (j < CC) av[j] = g_avg[b * CC + j];
    __syncthreads();
    float s = b1[j];
    const float* wr = w1 + (size_t)j * CC;
    #pragma unroll 16
    for (int c = 0; c < CC; ++c) s += av[c] * wr[c];
    g_wk[b * JDIM + j] = 1.0f / (1.0f + expf(-s));
}

// ---------------------------------------------------------------------------
// Kernel 3: depthwise 3x3 conv + conv_bias, fused with (x-y)*fs*x + y.
// Block: 256 threads = 4 row-slices x 64 col-groups over a 32-row x 256-col
// tile. Each thread produces a float4 of outputs per row for 8 rows, with a
// rolling 2-row x 6-float register window (one LDS.128+LDS.64 per row).
// Smem rows padded to 260 floats -> every per-thread base is 16B aligned.
// ---------------------------------------------------------------------------
#define TR 32
#define SWD 260

__global__ void conv_kernel(const float* __restrict__ x,
                            const float* __restrict__ fscale,
                            const float* __restrict__ conv_bias,
                            float* __restrict__ out) {
    const int bc   = blockIdx.y;          // 0..1023
    const int c    = bc & (CC - 1);
    const int row0 = blockIdx.x * TR;
    const int t    = threadIdx.x;         // 0..255

    __shared__ float sm[(TR + 2) * SWD];
    __shared__ float wsh[KPOS];

    if (t < KPOS) wsh[t] = g_wk[bc * KPOS + t];
    if (t < TR + 2) {                      // zero column halos
        sm[t * SWD + 0]   = 0.f;
        sm[t * SWD + 257] = 0.f;
    }

    const float* xp = x + (size_t)bc * HW;
    // Load 34 rows x 64 float4 (zero rows outside the image)
    #pragma unroll
    for (int i = t; i < (TR + 2) * 64; i += 256) {
        const int r  = i >> 6;
        const int c4 = i & 63;
        const int g  = row0 - 1 + r;
        float4 v = make_float4(0.f, 0.f, 0.f, 0.f);
        if ((unsigned)g < HH)
            v = reinterpret_cast<const float4*>(xp + (size_t)g * WW)[c4];
        float* d = &sm[r * SWD + 1 + c4 * 4];
        d[0] = v.x; d[1] = v.y; d[2] = v.z; d[3] = v.w;
    }
    __syncthreads();

    const float w0 = wsh[0], w1v = wsh[1], w2 = wsh[2];
    const float w3 = wsh[3], w4  = wsh[4], w5 = wsh[5];
    const float w6 = wsh[6], w7  = wsh[7], w8 = wsh[8];
    const float cb = conv_bias[c];
    const float fs = fscale[c];

    const int cg = t & 63;                 // column group: cols [4cg, 4cg+3]
    const int rs = t >> 6;                 // row slice 0..3 -> 8 rows each
    const int r0 = rs * 8;                 // first output row within tile
    const float* s0 = &sm[r0 * SWD + 4 * cg];   // 16B aligned

    float a0,a1,a2,a3,a4,a5, b0,b1,b2,b3,b4,b5;
    {
        float4 v4 = *reinterpret_cast<const float4*>(s0);
        float2 v2 = *reinterpret_cast<const float2*>(s0 + 4);
        a0=v4.x; a1=v4.y; a2=v4.z; a3=v4.w; a4=v2.x; a5=v2.y;
        v4 = *reinterpret_cast<const float4*>(s0 + SWD);
        v2 = *reinterpret_cast<const float2*>(s0 + SWD + 4);
        b0=v4.x; b1=v4.y; b2=v4.z; b3=v4.w; b4=v2.x; b5=v2.y;
    }

    float* op = out + (size_t)bc * HW + (size_t)(row0 + r0) * WW + 4 * cg;

    #pragma unroll
    for (int r = 0; r < 8; ++r) {
        const float* sc = s0 + (r + 2) * SWD;
        const float4 v4 = *reinterpret_cast<const float4*>(sc);
        const float2 v2 = *reinterpret_cast<const float2*>(sc + 4);
        const float c0=v4.x, c1=v4.y, c2=v4.z, c3=v4.w, c4f=v2.x, c5=v2.y;

        float4 o;
        {   // j = 0
            float y = cb + w0*a0 + w1v*a1 + w2*a2
                         + w3*b0 + w4 *b1 + w5*b2
                         + w6*c0 + w7 *c1 + w8*c2;
            const float xv = b1;
            o.x = (xv - y) * fs * xv + y;
        }
        {   // j = 1
            float y = cb + w0*a1 + w1v*a2 + w2*a3
                         + w3*b1 + w4 *b2 + w5*b3
                         + w6*c1 + w7 *c2 + w8*c3;
            const float xv = b2;
            o.y = (xv - y) * fs * xv + y;
        }
        {   // j = 2
            float y = cb + w0*a2 + w1v*a3 + w2*a4
                         + w3*b2 + w4 *b3 + w5*b4
                         + w6*c2 + w7 *c3 + w8*c4f;
            const float xv = b3;
            o.z = (xv - y) * fs * xv + y;
        }
        {   // j = 3
            float y = cb + w0*a3 + w1v*a4 + w2*a5
                         + w3*b3 + w4 *b4 + w5*b5
                         + w6*c3 + w7 *c4f + w8*c5;
            const float xv = b4;
            o.w = (xv - y) * fs * xv + y;
        }
        *reinterpret_cast<float4*>(op + (size_t)r * WW) = o;

        a0=b0; a1=b1; a2=b2; a3=b3; a4=b4; a5=b5;
        b0=c0; b1=c1; b2=c2; b3=c3; b4=c4f; b5=c5;
    }
}

// ---------------------------------------------------------------------------
// Launch: x, w1, b1, fscale, conv_bias (metadata order); out fp32.
// ---------------------------------------------------------------------------
extern "C" void kernel_launch(void* const* d_in, const int* in_sizes, int n_in,
                              void* d_out, int out_size) {
    const float* x         = (const float*)d_in[0];
    const float* w1        = (const float*)d_in[1];
    const float* b1        = (const float*)d_in[2];
    const float* fscale    = (const float*)d_in[3];
    const float* conv_bias = (const float*)d_in[4];
    float* out = (float*)d_out;

    avg_kernel<<<BB * CC, 256>>>(x);
    weight_kernel<<<BB, JDIM>>>(w1, b1);
    conv_kernel<<<dim3(HH / TR, BB * CC), 256>>>(x, fscale, conv_bias, out);
}